// round 11
// baseline (speedup 1.0000x reference)
#include <cuda_runtime.h>
#include <math.h>

// Problem constants
#define B_   4
#define T_   1024
#define C_   768
#define H_   12
#define D_   64
#define FA_  (3*C_)          // 2304
#define BHT_ (B_*H_*T_)      // 49152
#define ROWS_ (B_*T_)        // 4096
#define EPSY (1.0f/137.0f)

// ---------------- scratch (device globals: allocation-free) ----------------
__device__ float g_q [B_*H_*T_*D_];           // tf32-rounded
__device__ float g_k [B_*H_*T_*D_];           // tf32-rounded
__device__ float g_v [B_*H_*T_*D_];           // tf32-rounded
__device__ float g_ao[B_*T_*C_];              // attention output, tf32-rounded
__device__ float g_xt [ROWS_*C_];             // x, tf32-rounded
__device__ float g_wat[C_*FA_];               // W_attn, tf32-rounded
__device__ float g_wpt[C_*C_];                // W_proj, tf32-rounded
__device__ float g_xn [ROWS_];
__device__ float g_aon[ROWS_];
__device__ float g_aop[ROWS_*H_];             // per-head partial ||ao||^2
__device__ float g_wna[FA_];
__device__ float g_wnp[C_];
__device__ float g_qn [BHT_];
__device__ float g_kn [BHT_];

// ---------------- helpers ----------------
__device__ __forceinline__ unsigned f2tf32(float x) {
    unsigned r;
    asm("cvt.rna.tf32.f32 %0, %1;" : "=r"(r) : "f"(x));
    return r;
}

__device__ __forceinline__ void mma_tf32(float* d, const unsigned* a, const unsigned* b) {
    asm volatile("mma.sync.aligned.m16n8k8.row.col.f32.tf32.tf32.f32 "
        "{%0,%1,%2,%3}, {%4,%5,%6,%7}, {%8,%9}, {%0,%1,%2,%3};"
        : "+f"(d[0]), "+f"(d[1]), "+f"(d[2]), "+f"(d[3])
        : "r"(a[0]), "r"(a[1]), "r"(a[2]), "r"(a[3]), "r"(b[0]), "r"(b[1]));
}

__device__ __forceinline__ void cp16(void* smem, const void* gmem) {
    unsigned s = (unsigned)__cvta_generic_to_shared(smem);
    asm volatile("cp.async.cg.shared.global [%0], [%1], 16;" :: "r"(s), "l"(gmem));
}
#define CP_COMMIT() asm volatile("cp.async.commit_group;")
#define CP_WAIT(N)  asm volatile("cp.async.wait_group %0;" :: "n"(N))

// exp for yat scores: val >= 0, almost always << 1/16 -> 5-term Taylor;
// rare large values fall back to expf.
__device__ __forceinline__ float pexp(float x) {
    if (x < 0.0625f)
        return 1.f + x*(1.f + x*(0.5f + x*(0.16666667f + x*0.041666667f)));
    return expf(x);
}

// ---------------- rounding / norm kernels ----------------
// x: one warp per row: exact fp32 row norm + tf32-rounded copy.
__global__ __launch_bounds__(256) void round_x_norm(const float* __restrict__ in) {
    int warp = threadIdx.x >> 5, lane = threadIdx.x & 31;
    int r = blockIdx.x * 8 + warp;
    const float4* src = (const float4*)(in + (size_t)r * C_);
    float4* dst = (float4*)(g_xt + (size_t)r * C_);
    float s = 0.f;
    #pragma unroll
    for (int j = 0; j < 6; j++) {
        float4 v = src[lane + j * 32];
        s += v.x*v.x + v.y*v.y + v.z*v.z + v.w*v.w;
        v.x = __uint_as_float(f2tf32(v.x));
        v.y = __uint_as_float(f2tf32(v.y));
        v.z = __uint_as_float(f2tf32(v.z));
        v.w = __uint_as_float(f2tf32(v.w));
        dst[lane + j * 32] = v;
    }
    #pragma unroll
    for (int o = 16; o; o >>= 1) s += __shfl_xor_sync(0xffffffffu, s, o);
    if (lane == 0) g_xn[r] = s;
}

// W: single pass — exact col norms from original values + tf32-rounded copy.
// block = 8 cols x 32 row-strips.
__global__ __launch_bounds__(256) void roundnorm_w(const float* __restrict__ in,
                                                   float* __restrict__ wout,
                                                   float* __restrict__ nout, int ncols) {
    __shared__ float sh[32][9];
    int tx = threadIdx.x & 7, ty = threadIdx.x >> 3;
    int c = blockIdx.x * 8 + tx;
    float s = 0.f;
    #pragma unroll 4
    for (int r = ty; r < C_; r += 32) {
        float v = in[(size_t)r * ncols + c];
        s += v * v;
        wout[(size_t)r * ncols + c] = __uint_as_float(f2tf32(v));
    }
    sh[ty][tx] = s; __syncthreads();
    if (threadIdx.x < 8) {
        float t = 0.f;
        #pragma unroll
        for (int i = 0; i < 32; i++) t += sh[i][threadIdx.x];
        nout[blockIdx.x * 8 + threadIdx.x] = t;
    }
}

// sum per-head ao norm partials
__global__ void aon_sum() {
    int r = blockIdx.x * 256 + threadIdx.x;
    if (r >= ROWS_) return;
    float s = 0.f;
    #pragma unroll
    for (int h = 0; h < H_; h++) s += g_aop[(size_t)r * H_ + h];
    g_aon[r] = s;
}

// ============ tf32 yat GEMM: 128x128 tile, 8 warps of 32x64, cp.async 2-stage ============
#define AST 36
#define BST 136
#define GEMM_SMEM ((2*128*AST + 2*32*BST)*4)

template<int LDN>
__device__ __forceinline__ void gemm_body(const float* __restrict__ Asrc,
                                          const float* __restrict__ Bsrc,
                                          float acc[2][8][4],
                                          int rowBase, int colBase) {
    extern __shared__ float smf[];
    float* Asf[2] = { smf, smf + 128*AST };
    float* Bsf[2] = { smf + 2*128*AST, smf + 2*128*AST + 32*BST };
    const int tid  = threadIdx.x;
    const int lane = tid & 31;
    const int warp = tid >> 5;
    const int g = lane >> 2, t = lane & 3;
    const int wm = (warp & 3) * 32, wn = (warp >> 2) * 64;
    const int arow = tid >> 1, ahalf = (tid & 1) * 16;
    const int brow = tid >> 3, bseg = (tid & 7) * 16;
    const int NIT = C_ / 32;

    {
        const float* Ap = Asrc + (size_t)(rowBase + arow) * C_ + ahalf;
        #pragma unroll
        for (int j = 0; j < 4; j++) cp16(&Asf[0][arow*AST + ahalf + j*4], Ap + j*4);
        const float* Bp = Bsrc + (size_t)brow * LDN + colBase + bseg;
        #pragma unroll
        for (int j = 0; j < 4; j++) cp16(&Bsf[0][brow*BST + bseg + j*4], Bp + j*4);
        CP_COMMIT();
    }

    for (int it = 0; it < NIT; it++) {
        CP_WAIT(0);
        __syncthreads();
        if (it + 1 < NIT) {
            int s = (it + 1) & 1, k0 = (it + 1) * 32;
            const float* Ap = Asrc + (size_t)(rowBase + arow) * C_ + k0 + ahalf;
            #pragma unroll
            for (int j = 0; j < 4; j++) cp16(&Asf[s][arow*AST + ahalf + j*4], Ap + j*4);
            const float* Bp = Bsrc + (size_t)(k0 + brow) * LDN + colBase + bseg;
            #pragma unroll
            for (int j = 0; j < 4; j++) cp16(&Bsf[s][brow*BST + bseg + j*4], Bp + j*4);
            CP_COMMIT();
        }
        const float* Af = Asf[it & 1];
        const float* Bf = Bsf[it & 1];
        #pragma unroll
        for (int kk8 = 0; kk8 < 4; kk8++) {
            int kk = kk8 * 8;
            unsigned a[2][4], b[8][2];
            #pragma unroll
            for (int mt = 0; mt < 2; mt++) {
                int m0 = wm + mt * 16;
                a[mt][0] = __float_as_uint(Af[(m0 + g    ) * AST + kk + t]);
                a[mt][1] = __float_as_uint(Af[(m0 + g + 8) * AST + kk + t]);
                a[mt][2] = __float_as_uint(Af[(m0 + g    ) * AST + kk + t + 4]);
                a[mt][3] = __float_as_uint(Af[(m0 + g + 8) * AST + kk + t + 4]);
            }
            #pragma unroll
            for (int nt = 0; nt < 8; nt++) {
                int n0 = wn + nt * 8;
                b[nt][0] = __float_as_uint(Bf[(kk + t    ) * BST + n0 + g]);
                b[nt][1] = __float_as_uint(Bf[(kk + t + 4) * BST + n0 + g]);
            }
            #pragma unroll
            for (int mt = 0; mt < 2; mt++)
                #pragma unroll
                for (int nt = 0; nt < 8; nt++)
                    mma_tf32(acc[mt][nt], a[mt], b[nt]);
        }
        __syncthreads();
    }
}

__global__ __launch_bounds__(256) void qkv_tc(const float* __restrict__ bias,
                                              const float* __restrict__ alpha) {
    const int rowBase = blockIdx.y * 128;
    const int colBase = blockIdx.x * 128;
    float acc[2][8][4];
    #pragma unroll
    for (int i = 0; i < 2; i++)
        #pragma unroll
        for (int j = 0; j < 8; j++)
            #pragma unroll
            for (int e = 0; e < 4; e++) acc[i][j][e] = 0.f;

    gemm_body<FA_>(g_xt, g_wat, acc, rowBase, colBase);

    const int lane = threadIdx.x & 31, warp = threadIdx.x >> 5;
    const int g = lane >> 2, t = lane & 3;
    const int wm = (warp & 3) * 32, wn = (warp >> 2) * 64;
    const int gg = (colBase + wn) >> 6;          // warp-uniform head group
    const int h = gg % 12;
    float* dst = (gg < 12) ? g_q : ((gg < 24) ? g_k : g_v);
    float ysc = powf(sqrtf((float)FA_) / log1pf((float)FA_), alpha[0]);

    #pragma unroll
    for (int mt = 0; mt < 2; mt++) {
        #pragma unroll
        for (int e2 = 0; e2 < 2; e2++) {
            int r = rowBase + wm + mt * 16 + g + e2 * 8;
            float xn = g_xn[r];
            int bb = r >> 10, tt = r & (T_ - 1);
            float ns = 0.f;
            float* drow = dst + (((size_t)bb * H_ + h) * T_ + tt) * D_;
            #pragma unroll
            for (int nt = 0; nt < 8; nt++) {
                #pragma unroll
                for (int e1 = 0; e1 < 2; e1++) {
                    int c = colBase + wn + nt * 8 + t * 2 + e1;
                    float dot = acc[mt][nt][e2 * 2 + e1];
                    float dist = xn + g_wna[c] - 2.f * dot;
                    float y = (__fdividef(dot * dot, dist + EPSY) + bias[c]) * ysc;
                    float yr = __uint_as_float(f2tf32(y));
                    drow[c & 63] = yr;
                    ns += yr * yr;
                }
            }
            if (gg < 24) {
                ns += __shfl_xor_sync(0xffffffffu, ns, 1);
                ns += __shfl_xor_sync(0xffffffffu, ns, 2);
                if (t == 0) {
                    float* np = (gg < 12) ? g_qn : g_kn;
                    np[((size_t)bb * H_ + h) * T_ + tt] = ns;
                }
            }
        }
    }
}

__global__ __launch_bounds__(256) void proj_tc(const float* __restrict__ bias,
                                               const float* __restrict__ alpha,
                                               float* __restrict__ out) {
    const int rowBase = blockIdx.y * 128;
    const int colBase = blockIdx.x * 128;
    float acc[2][8][4];
    #pragma unroll
    for (int i = 0; i < 2; i++)
        #pragma unroll
        for (int j = 0; j < 8; j++)
            #pragma unroll
            for (int e = 0; e < 4; e++) acc[i][j][e] = 0.f;

    gemm_body<C_>(g_ao, g_wpt, acc, rowBase, colBase);

    const int lane = threadIdx.x & 31, warp = threadIdx.x >> 5;
    const int g = lane >> 2, t = lane & 3;
    const int wm = (warp & 3) * 32, wn = (warp >> 2) * 64;
    float ysc = powf(sqrtf((float)C_) / log1pf((float)C_), alpha[0]);
    #pragma unroll
    for (int mt = 0; mt < 2; mt++) {
        #pragma unroll
        for (int e2 = 0; e2 < 2; e2++) {
            int r = rowBase + wm + mt * 16 + g + e2 * 8;
            float xn = g_aon[r];
            #pragma unroll
            for (int nt = 0; nt < 8; nt++) {
                #pragma unroll
                for (int e1 = 0; e1 < 2; e1++) {
                    int c = colBase + wn + nt * 8 + t * 2 + e1;
                    float dot = acc[mt][nt][e2 * 2 + e1];
                    float dist = xn + g_wnp[c] - 2.f * dot;
                    out[(size_t)r * C_ + c] = (__fdividef(dot * dot, dist + EPSY) + bias[c]) * ysc;
                }
            }
        }
    }
}

// ============ fused yat attention: 128 q-rows/block, 8 warps, no-max softmax ============
// yat scores are >= 0 and tiny; softmax without max-subtraction is exact here
// (pexp falls back to expf for any value above the Taylor window).
#define FSTR 72
#define ATTN_SMEM ((128*FSTR + 2*64*FSTR + 64)*4)

__global__ __launch_bounds__(256) void attn_fused() {
    const int br = (int)gridDim.x - 1 - (int)blockIdx.x;   // big tiles first
    const int bh = blockIdx.y;
    const float* Qg = g_q + ((size_t)bh * T_ + br * 128) * D_;
    const float* Kg = g_k + (size_t)bh * T_ * D_;
    const float* Vg = g_v + (size_t)bh * T_ * D_;
    const float* kng = g_kn + bh * T_;

    extern __shared__ unsigned ash[];
    unsigned* Ps = ash;                      // Q then P (128 rows)
    unsigned* Ks = ash + 128 * FSTR;
    unsigned* Vs = Ks + 64 * FSTR;
    float*   knf = (float*)(Vs + 64 * FSTR);

    const int tid = threadIdx.x, lane = tid & 31, warp = tid >> 5;
    const int g = lane >> 2, t = lane & 3;
    const int wq = warp * 16;
    const int qrow = tid >> 1, qhalf = (tid & 1) * 32;     // Q staging: 128 rows
    const int krow = tid >> 2, kseg = (tid & 3) * 16;      // K/V staging: 64 rows

    // ---- prologue: stage Q, K0+kn0, V0 ----
    {
        const float* p = Qg + (size_t)qrow * D_ + qhalf;
        #pragma unroll
        for (int j = 0; j < 8; j++) cp16(&Ps[qrow*FSTR + qhalf + j*4], p + j*4);
        CP_COMMIT();                                        // GQ
        const float* pk = Kg + (size_t)krow * D_ + kseg;
        #pragma unroll
        for (int j = 0; j < 4; j++) cp16(&Ks[krow*FSTR + kseg + j*4], pk + j*4);
        if (tid < 16) cp16(&knf[tid*4], kng + tid*4);
        CP_COMMIT();                                        // GK0
        const float* pv = Vg + (size_t)krow * D_ + kseg;
        #pragma unroll
        for (int j = 0; j < 4; j++) cp16(&Vs[krow*FSTR + kseg + j*4], pv + j*4);
        CP_COMMIT();                                        // GV0
    }
    CP_WAIT(2);            // Q done; warp staged exactly its own 16 rows
    __syncwarp();

    unsigned qa[8][4];
    #pragma unroll
    for (int kk8 = 0; kk8 < 8; kk8++) {
        int kk = kk8 * 8;
        qa[kk8][0] = Ps[(wq + g    ) * FSTR + kk + t];
        qa[kk8][1] = Ps[(wq + g + 8) * FSTR + kk + t];
        qa[kk8][2] = Ps[(wq + g    ) * FSTR + kk + t + 4];
        qa[kk8][3] = Ps[(wq + g + 8) * FSTR + kk + t + 4];
    }
    const float qn0 = g_qn[bh * T_ + br * 128 + wq + g];
    const float qn1 = g_qn[bh * T_ + br * 128 + wq + g + 8];

    float O[8][4];
    #pragma unroll
    for (int i = 0; i < 8; i++)
        #pragma unroll
        for (int e = 0; e < 4; e++) O[i][e] = 0.f;
    float l0 = 0.f, l1 = 0.f;

    const int gi0 = br * 128 + wq + g;
    const int gi1 = gi0 + 8;
    const int KT = 2 * br + 1;

    for (int kt = 0; kt <= KT; kt++) {
        CP_WAIT(1);          // K(kt)+kn done; V(kt) may be in flight
        __syncthreads();

        // ---- S = Q K^T ----
        float acc[8][4];
        #pragma unroll
        for (int i = 0; i < 8; i++)
            #pragma unroll
            for (int e = 0; e < 4; e++) acc[i][e] = 0.f;
        #pragma unroll
        for (int kk8 = 0; kk8 < 8; kk8++) {
            #pragma unroll
            for (int nt = 0; nt < 8; nt++) {
                unsigned b[2];
                b[0] = Ks[(nt * 8 + g) * FSTR + kk8 * 8 + t];
                b[1] = Ks[(nt * 8 + g) * FSTR + kk8 * 8 + t + 4];
                mma_tf32(acc[nt], qa[kk8], b);
            }
        }

        // ---- yat -> P = exp(val) (no max needed), causal mask via p=0 ----
        const bool dz = ((kt << 6) + 63) > (br * 128 + wq);   // warp-uniform diag zone
        float sum0 = 0.f, sum1 = 0.f;
        #pragma unroll
        for (int nt = 0; nt < 8; nt++) {
            int lc = nt * 8 + 2 * t;
            int j0 = (kt << 6) + lc;
            float kna = knf[lc], knb = knf[lc + 1];
            float s00 = acc[nt][0] * 0.125f, s01 = acc[nt][1] * 0.125f;
            float s10 = acc[nt][2] * 0.125f, s11 = acc[nt][3] * 0.125f;
            float p00 = pexp(__fdividef(s00 * s00, qn0 + kna - 2.f * s00 + EPSY));
            float p01 = pexp(__fdividef(s01 * s01, qn0 + knb - 2.f * s01 + EPSY));
            float p10 = pexp(__fdividef(s10 * s10, qn1 + kna - 2.f * s10 + EPSY));
            float p11 = pexp(__fdividef(s11 * s11, qn1 + knb - 2.f * s11 + EPSY));
            if (dz) {
                if (j0     > gi0) p00 = 0.f;
                if (j0 + 1 > gi0) p01 = 0.f;
                if (j0     > gi1) p10 = 0.f;
                if (j0 + 1 > gi1) p11 = 0.f;
            }
            sum0 += p00 + p01; sum1 += p10 + p11;
            Ps[(wq + g    ) * FSTR + lc    ] = f2tf32(p00);
            Ps[(wq + g    ) * FSTR + lc + 1] = f2tf32(p01);
            Ps[(wq + g + 8) * FSTR + lc    ] = f2tf32(p10);
            Ps[(wq + g + 8) * FSTR + lc + 1] = f2tf32(p11);
        }
        sum0 += __shfl_xor_sync(0xffffffffu, sum0, 1);
        sum0 += __shfl_xor_sync(0xffffffffu, sum0, 2);
        sum1 += __shfl_xor_sync(0xffffffffu, sum1, 1);
        sum1 += __shfl_xor_sync(0xffffffffu, sum1, 2);
        l0 += sum0;
        l1 += sum1;

        CP_WAIT(0);          // V(kt) done
        __syncthreads();     // V visible; all warps done reading Ks

        if (kt < KT) {       // prefetch K(kt+1): overlaps PV MMA
            const float* pk = Kg + (size_t)(kt + 1) * 64 * D_ + (size_t)krow * D_ + kseg;
            #pragma unroll
            for (int j = 0; j < 4; j++) cp16(&Ks[krow*FSTR + kseg + j*4], pk + j*4);
            if (tid < 16) cp16(&knf[tid*4], kng + (kt + 1) * 64 + tid*4);
            CP_COMMIT();
        }

        // ---- O += P V ----
        #pragma unroll
        for (int kk8 = 0; kk8 < 8; kk8++) {
            unsigned a[4];
            a[0] = Ps[(wq + g    ) * FSTR + kk8 * 8 + t];
            a[1] = Ps[(wq + g + 8) * FSTR + kk8 * 8 + t];
            a[2] = Ps[(wq + g    ) * FSTR + kk8 * 8 + t + 4];
            a[3] = Ps[(wq + g + 8) * FSTR + kk8 * 8 + t + 4];
            #pragma unroll
            for (int nt = 0; nt < 8; nt++) {
                unsigned b[2];
                b[0] = Vs[(kk8 * 8 + t    ) * FSTR + nt * 8 + g];
                b[1] = Vs[(kk8 * 8 + t + 4) * FSTR + nt * 8 + g];
                mma_tf32(O[nt], a, b);
            }
        }
        __syncthreads();     // all warps done reading Vs

        if (kt < KT) {       // prefetch V(kt+1): overlaps next S phase
            const float* pv = Vg + (size_t)(kt + 1) * 64 * D_ + (size_t)krow * D_ + kseg;
            #pragma unroll
            for (int j = 0; j < 4; j++) cp16(&Vs[krow*FSTR + kseg + j*4], pv + j*4);
            CP_COMMIT();
        }
    }

    // ---- epilogue: normalize, tf32-round, write [B,T,C], per-head norm partials ----
    float inv0 = __fdividef(1.f, l0), inv1 = __fdividef(1.f, l1);
    int bb = bh / H_, h = bh % H_;
    size_t rr0 = (size_t)bb * T_ + br * 128 + wq + g;
    size_t rr1 = rr0 + 8;
    float* ao0 = g_ao + rr0 * C_ + h * D_;
    float* ao1 = g_ao + rr1 * C_ + h * D_;
    float n0 = 0.f, n1 = 0.f;
    #pragma unroll
    for (int nt = 0; nt < 8; nt++) {
        int lc = nt * 8 + 2 * t;
        float2 w0, w1;
        w0.x = __uint_as_float(f2tf32(O[nt][0] * inv0));
        w0.y = __uint_as_float(f2tf32(O[nt][1] * inv0));
        w1.x = __uint_as_float(f2tf32(O[nt][2] * inv1));
        w1.y = __uint_as_float(f2tf32(O[nt][3] * inv1));
        n0 += w0.x*w0.x + w0.y*w0.y;
        n1 += w1.x*w1.x + w1.y*w1.y;
        *(float2*)(ao0 + lc) = w0;
        *(float2*)(ao1 + lc) = w1;
    }
    n0 += __shfl_xor_sync(0xffffffffu, n0, 1);
    n0 += __shfl_xor_sync(0xffffffffu, n0, 2);
    n1 += __shfl_xor_sync(0xffffffffu, n1, 1);
    n1 += __shfl_xor_sync(0xffffffffu, n1, 2);
    if (t == 0) {
        g_aop[rr0 * H_ + h] = n0;
        g_aop[rr1 * H_ + h] = n1;
    }
}

// ---------------- launch ----------------
extern "C" void kernel_launch(void* const* d_in, const int* in_sizes, int n_in,
                              void* d_out, int out_size) {
    const float* x  = (const float*)d_in[0];
    // d_in[1] = causal mask (bool) — structure known, unused
    const float* Wa = (const float*)d_in[2];
    const float* ba = (const float*)d_in[3];
    const float* aa = (const float*)d_in[4];
    const float* Wp = (const float*)d_in[5];
    const float* bp = (const float*)d_in[6];
    const float* ap = (const float*)d_in[7];
    float* out = (float*)d_out;

    static int attr_done = 0;
    if (!attr_done) {
        cudaFuncSetAttribute(qkv_tc,     cudaFuncAttributeMaxDynamicSharedMemorySize, GEMM_SMEM);
        cudaFuncSetAttribute(proj_tc,    cudaFuncAttributeMaxDynamicSharedMemorySize, GEMM_SMEM);
        cudaFuncSetAttribute(attn_fused, cudaFuncAttributeMaxDynamicSharedMemorySize, ATTN_SMEM);
        attr_done = 1;
    }

    float* wat; cudaGetSymbolAddress((void**)&wat, g_wat);
    float* wpt; cudaGetSymbolAddress((void**)&wpt, g_wpt);
    float* wna; cudaGetSymbolAddress((void**)&wna, g_wna);
    float* wnp; cudaGetSymbolAddress((void**)&wnp, g_wnp);

    round_x_norm<<<ROWS_/8, 256>>>(x);
    roundnorm_w <<<FA_/8, 256>>>(Wa, wat, wna, FA_);
    roundnorm_w <<<C_/8,  256>>>(Wp, wpt, wnp, C_);
    qkv_tc      <<<dim3(FA_/128, ROWS_/128), 256, GEMM_SMEM>>>(ba, aa);
    attn_fused  <<<dim3(T_/128, B_*H_), 256, ATTN_SMEM>>>();
    aon_sum     <<<ROWS_/256, 256>>>();
    proj_tc     <<<dim3(C_/128, ROWS_/128), 256, GEMM_SMEM>>>(bp, ap, out);
}

// round 14
// speedup vs baseline: 1.0364x; 1.0364x over previous
#include <cuda_runtime.h>
#include <math.h>

// Problem constants
#define B_   4
#define T_   1024
#define C_   768
#define H_   12
#define D_   64
#define FA_  (3*C_)          // 2304
#define BHT_ (B_*H_*T_)      // 49152
#define ROWS_ (B_*T_)        // 4096
#define EPSY (1.0f/137.0f)

// ---------------- scratch (device globals: allocation-free) ----------------
__device__ float g_q [B_*H_*T_*D_];           // tf32-rounded
__device__ float g_k [B_*H_*T_*D_];
__device__ float g_v [B_*H_*T_*D_];
__device__ float g_ao[B_*T_*C_];              // attention output, tf32-rounded
__device__ float g_xt [ROWS_*C_];             // x, tf32-rounded
__device__ float g_wat[C_*FA_];               // W_attn, tf32-rounded
__device__ float g_wpt[C_*C_];                // W_proj, tf32-rounded
__device__ float g_xn [ROWS_];
__device__ float g_aon[ROWS_];
__device__ float g_aop[ROWS_*H_];             // per-head partial ||ao||^2
__device__ float g_wna[FA_];
__device__ float g_wnp[C_];
__device__ float g_qn [BHT_];
__device__ float g_kn [BHT_];

// ---------------- helpers ----------------
__device__ __forceinline__ unsigned f2tf32(float x) {
    unsigned r; asm("cvt.rna.tf32.f32 %0, %1;" : "=r"(r) : "f"(x)); return r;
}
__device__ __forceinline__ void mma_tf32(float* d, const unsigned* a, const unsigned* b) {
    asm volatile("mma.sync.aligned.m16n8k8.row.col.f32.tf32.tf32.f32 "
        "{%0,%1,%2,%3}, {%4,%5,%6,%7}, {%8,%9}, {%0,%1,%2,%3};"
        : "+f"(d[0]), "+f"(d[1]), "+f"(d[2]), "+f"(d[3])
        : "r"(a[0]), "r"(a[1]), "r"(a[2]), "r"(a[3]), "r"(b[0]), "r"(b[1]));
}
__device__ __forceinline__ void cp16(void* smem, const void* gmem) {
    unsigned s = (unsigned)__cvta_generic_to_shared(smem);
    asm volatile("cp.async.cg.shared.global [%0], [%1], 16;" :: "r"(s), "l"(gmem));
}
#define CP_COMMIT() asm volatile("cp.async.commit_group;")
#define CP_WAIT(N)  asm volatile("cp.async.wait_group %0;" :: "n"(N))

// exp for yat scores: val >= 0, almost always << 1/16 -> 5-term Taylor;
// rare large values fall back to expf.
__device__ __forceinline__ float pexp(float x) {
    if (x < 0.0625f)
        return 1.f + x*(1.f + x*(0.5f + x*(0.16666667f + x*0.041666667f)));
    return expf(x);
}

// ---------------- rounding / norm kernels ----------------
__global__ __launch_bounds__(256) void round_x_norm(const float* __restrict__ in) {
    int warp = threadIdx.x >> 5, lane = threadIdx.x & 31;
    int r = blockIdx.x * 8 + warp;
    const float4* src = (const float4*)(in + (size_t)r * C_);
    float4* dst = (float4*)(g_xt + (size_t)r * C_);
    float s = 0.f;
    #pragma unroll
    for (int j = 0; j < 6; j++) {
        float4 v = src[lane + j * 32];
        s += v.x*v.x + v.y*v.y + v.z*v.z + v.w*v.w;
        v.x = __uint_as_float(f2tf32(v.x));
        v.y = __uint_as_float(f2tf32(v.y));
        v.z = __uint_as_float(f2tf32(v.z));
        v.w = __uint_as_float(f2tf32(v.w));
        dst[lane + j * 32] = v;
    }
    #pragma unroll
    for (int o = 16; o; o >>= 1) s += __shfl_xor_sync(0xffffffffu, s, o);
    if (lane == 0) g_xn[r] = s;
}

__global__ __launch_bounds__(256) void roundnorm_w(const float* __restrict__ in,
                                                   float* __restrict__ wout,
                                                   float* __restrict__ nout, int ncols) {
    __shared__ float sh[32][9];
    int tx = threadIdx.x & 7, ty = threadIdx.x >> 3;
    int c = blockIdx.x * 8 + tx;
    float s = 0.f;
    #pragma unroll 4
    for (int r = ty; r < C_; r += 32) {
        float v = in[(size_t)r * ncols + c];
        s += v * v;
        wout[(size_t)r * ncols + c] = __uint_as_float(f2tf32(v));
    }
    sh[ty][tx] = s; __syncthreads();
    if (threadIdx.x < 8) {
        float t = 0.f;
        #pragma unroll
        for (int i = 0; i < 32; i++) t += sh[i][threadIdx.x];
        nout[blockIdx.x * 8 + threadIdx.x] = t;
    }
}

__global__ void aon_sum() {
    int r = blockIdx.x * 256 + threadIdx.x;
    if (r >= ROWS_) return;
    float s = 0.f;
    #pragma unroll
    for (int h = 0; h < H_; h++) s += g_aop[(size_t)r * H_ + h];
    g_aon[r] = s;
}

// ============ tf32 yat GEMM: 128x128 tile, 8 warps of 32x64 ============
// cp.async 3-slot ring, prefetch distance 2, ONE __syncthreads per k-iter.
#define AST 36
#define BST 136
#define STAGEF (128*AST + 32*BST)          // floats per stage (8960)
#define GEMM_SMEM (3*STAGEF*4)             // 107,520 B -> 2 CTAs/SM

template<int LDN>
__device__ __forceinline__ void gemm_body(const float* __restrict__ Asrc,
                                          const float* __restrict__ Bsrc,
                                          float acc[2][8][4],
                                          int rowBase, int colBase) {
    extern __shared__ float smf[];
    const int tid  = threadIdx.x;
    const int lane = tid & 31;
    const int warp = tid >> 5;
    const int g = lane >> 2, t = lane & 3;
    const int wm = (warp & 3) * 32, wn = (warp >> 2) * 64;
    const int arow = tid >> 1, ahalf = (tid & 1) * 16;
    const int brow = tid >> 3, bseg = (tid & 7) * 16;
    const int NIT = C_ / 32;               // 24

    const float* Abase = Asrc + (size_t)(rowBase + arow) * C_ + ahalf;
    const float* Bbase = Bsrc + colBase + bseg + (size_t)brow * LDN;

    // prologue: stages 0, 1
    #pragma unroll
    for (int st = 0; st < 2; st++) {
        float* As = smf + st * STAGEF;
        float* Bs = As + 128 * AST;
        const float* Ap = Abase + st * 32;
        #pragma unroll
        for (int j = 0; j < 4; j++) cp16(&As[arow*AST + ahalf + j*4], Ap + j*4);
        const float* Bp = Bbase + (size_t)(st * 32) * LDN;
        #pragma unroll
        for (int j = 0; j < 4; j++) cp16(&Bs[brow*BST + bseg + j*4], Bp + j*4);
        CP_COMMIT();
    }

    int slot = 0, pslot = 2;
    for (int it = 0; it < NIT; it++) {
        if (it < NIT - 1) { CP_WAIT(1); } else { CP_WAIT(0); }
        __syncthreads();                   // stage `it` ready; slot `pslot` free

        if (it + 2 < NIT) {                // prefetch stage it+2 (distance 2)
            float* As = smf + pslot * STAGEF;
            float* Bs = As + 128 * AST;
            const float* Ap = Abase + (it + 2) * 32;
            #pragma unroll
            for (int j = 0; j < 4; j++) cp16(&As[arow*AST + ahalf + j*4], Ap + j*4);
            const float* Bp = Bbase + (size_t)((it + 2) * 32) * LDN;
            #pragma unroll
            for (int j = 0; j < 4; j++) cp16(&Bs[brow*BST + bseg + j*4], Bp + j*4);
            CP_COMMIT();
        }

        const float* Af = smf + slot * STAGEF;
        const float* Bf = Af + 128 * AST;
        #pragma unroll
        for (int kk8 = 0; kk8 < 4; kk8++) {
            int kk = kk8 * 8;
            unsigned a[2][4], b[8][2];
            #pragma unroll
            for (int mt = 0; mt < 2; mt++) {
                int m0 = wm + mt * 16;
                a[mt][0] = __float_as_uint(Af[(m0 + g    ) * AST + kk + t]);
                a[mt][1] = __float_as_uint(Af[(m0 + g + 8) * AST + kk + t]);
                a[mt][2] = __float_as_uint(Af[(m0 + g    ) * AST + kk + t + 4]);
                a[mt][3] = __float_as_uint(Af[(m0 + g + 8) * AST + kk + t + 4]);
            }
            #pragma unroll
            for (int nt = 0; nt < 8; nt++) {
                int n0 = wn + nt * 8;
                b[nt][0] = __float_as_uint(Bf[(kk + t    ) * BST + n0 + g]);
                b[nt][1] = __float_as_uint(Bf[(kk + t + 4) * BST + n0 + g]);
            }
            #pragma unroll
            for (int mt = 0; mt < 2; mt++)
                #pragma unroll
                for (int nt = 0; nt < 8; nt++)
                    mma_tf32(acc[mt][nt], a[mt], b[nt]);
        }
        slot  = (slot  == 2) ? 0 : slot + 1;
        pslot = (pslot == 2) ? 0 : pslot + 1;
    }
}

__global__ __launch_bounds__(256) void qkv_tc(const float* __restrict__ bias,
                                              const float* __restrict__ alpha) {
    const int rowBase = blockIdx.y * 128;
    const int colBase = blockIdx.x * 128;
    float acc[2][8][4];
    #pragma unroll
    for (int i = 0; i < 2; i++)
        #pragma unroll
        for (int j = 0; j < 8; j++)
            #pragma unroll
            for (int e = 0; e < 4; e++) acc[i][j][e] = 0.f;

    gemm_body<FA_>(g_xt, g_wat, acc, rowBase, colBase);

    const int lane = threadIdx.x & 31, warp = threadIdx.x >> 5;
    const int g = lane >> 2, t = lane & 3;
    const int wm = (warp & 3) * 32, wn = (warp >> 2) * 64;
    const int gg = (colBase + wn) >> 6;          // warp-uniform head group
    const int h = gg % 12;
    float* dst = (gg < 12) ? g_q : ((gg < 24) ? g_k : g_v);
    float ysc = powf(sqrtf((float)FA_) / log1pf((float)FA_), alpha[0]);

    #pragma unroll
    for (int mt = 0; mt < 2; mt++) {
        #pragma unroll
        for (int e2 = 0; e2 < 2; e2++) {
            int r = rowBase + wm + mt * 16 + g + e2 * 8;
            float xn = g_xn[r];
            int bb = r >> 10, tt = r & (T_ - 1);
            float ns = 0.f;
            float* drow = dst + (((size_t)bb * H_ + h) * T_ + tt) * D_;
            #pragma unroll
            for (int nt = 0; nt < 8; nt++) {
                #pragma unroll
                for (int e1 = 0; e1 < 2; e1++) {
                    int c = colBase + wn + nt * 8 + t * 2 + e1;
                    float dot = acc[mt][nt][e2 * 2 + e1];
                    float dist = xn + g_wna[c] - 2.f * dot;
                    float y = (__fdividef(dot * dot, dist + EPSY) + bias[c]) * ysc;
                    float yr = __uint_as_float(f2tf32(y));
                    drow[c & 63] = yr;
                    ns += yr * yr;
                }
            }
            if (gg < 24) {
                ns += __shfl_xor_sync(0xffffffffu, ns, 1);
                ns += __shfl_xor_sync(0xffffffffu, ns, 2);
                if (t == 0) {
                    float* np = (gg < 12) ? g_qn : g_kn;
                    np[((size_t)bb * H_ + h) * T_ + tt] = ns;
                }
            }
        }
    }
}

__global__ __launch_bounds__(256) void proj_tc(const float* __restrict__ bias,
                                               const float* __restrict__ alpha,
                                               float* __restrict__ out) {
    const int rowBase = blockIdx.y * 128;
    const int colBase = blockIdx.x * 128;
    float acc[2][8][4];
    #pragma unroll
    for (int i = 0; i < 2; i++)
        #pragma unroll
        for (int j = 0; j < 8; j++)
            #pragma unroll
            for (int e = 0; e < 4; e++) acc[i][j][e] = 0.f;

    gemm_body<C_>(g_ao, g_wpt, acc, rowBase, colBase);

    const int lane = threadIdx.x & 31, warp = threadIdx.x >> 5;
    const int g = lane >> 2, t = lane & 3;
    const int wm = (warp & 3) * 32, wn = (warp >> 2) * 64;
    float ysc = powf(sqrtf((float)C_) / log1pf((float)C_), alpha[0]);
    #pragma unroll
    for (int mt = 0; mt < 2; mt++) {
        #pragma unroll
        for (int e2 = 0; e2 < 2; e2++) {
            int r = rowBase + wm + mt * 16 + g + e2 * 8;
            float xn = g_aon[r];
            #pragma unroll
            for (int nt = 0; nt < 8; nt++) {
                #pragma unroll
                for (int e1 = 0; e1 < 2; e1++) {
                    int c = colBase + wn + nt * 8 + t * 2 + e1;
                    float dot = acc[mt][nt][e2 * 2 + e1];
                    float dist = xn + g_wnp[c] - 2.f * dot;
                    out[(size_t)r * C_ + c] = (__fdividef(dot * dot, dist + EPSY) + bias[c]) * ysc;
                }
            }
        }
    }
}

// ============ fused yat attention: 128 q-rows/block, 8 warps, no-max softmax ============
#define FSTR 72
#define ATTN_SMEM ((128*FSTR + 2*64*FSTR + 64)*4)

__global__ __launch_bounds__(256) void attn_fused() {
    const int br = (int)gridDim.x - 1 - (int)blockIdx.x;   // big tiles first
    const int bh = blockIdx.y;
    const float* Qg = g_q + ((size_t)bh * T_ + br * 128) * D_;
    const float* Kg = g_k + (size_t)bh * T_ * D_;
    const float* Vg = g_v + (size_t)bh * T_ * D_;
    const float* kng = g_kn + bh * T_;

    extern __shared__ unsigned ash[];
    unsigned* Ps = ash;
    unsigned* Ks = ash + 128 * FSTR;
    unsigned* Vs = Ks + 64 * FSTR;
    float*   knf = (float*)(Vs + 64 * FSTR);

    const int tid = threadIdx.x, lane = tid & 31, warp = tid >> 5;
    const int g = lane >> 2, t = lane & 3;
    const int wq = warp * 16;
    const int qrow = tid >> 1, qhalf = (tid & 1) * 32;
    const int krow = tid >> 2, kseg = (tid & 3) * 16;

    {
        const float* p = Qg + (size_t)qrow * D_ + qhalf;
        #pragma unroll
        for (int j = 0; j < 8; j++) cp16(&Ps[qrow*FSTR + qhalf + j*4], p + j*4);
        CP_COMMIT();
        const float* pk = Kg + (size_t)krow * D_ + kseg;
        #pragma unroll
        for (int j = 0; j < 4; j++) cp16(&Ks[krow*FSTR + kseg + j*4], pk + j*4);
        if (tid < 16) cp16(&knf[tid*4], kng + tid*4);
        CP_COMMIT();
        const float* pv = Vg + (size_t)krow * D_ + kseg;
        #pragma unroll
        for (int j = 0; j < 4; j++) cp16(&Vs[krow*FSTR + kseg + j*4], pv + j*4);
        CP_COMMIT();
    }
    CP_WAIT(2);
    __syncwarp();

    unsigned qa[8][4];
    #pragma unroll
    for (int kk8 = 0; kk8 < 8; kk8++) {
        int kk = kk8 * 8;
        qa[kk8][0] = Ps[(wq + g    ) * FSTR + kk + t];
        qa[kk8][1] = Ps[(wq + g + 8) * FSTR + kk + t];
        qa[kk8][2] = Ps[(wq + g    ) * FSTR + kk + t + 4];
        qa[kk8][3] = Ps[(wq + g + 8) * FSTR + kk + t + 4];
    }
    const float qn0 = g_qn[bh * T_ + br * 128 + wq + g];
    const float qn1 = g_qn[bh * T_ + br * 128 + wq + g + 8];

    float O[8][4];
    #pragma unroll
    for (int i = 0; i < 8; i++)
        #pragma unroll
        for (int e = 0; e < 4; e++) O[i][e] = 0.f;
    float l0 = 0.f, l1 = 0.f;

    const int gi0 = br * 128 + wq + g;
    const int gi1 = gi0 + 8;
    const int KT = 2 * br + 1;

    for (int kt = 0; kt <= KT; kt++) {
        CP_WAIT(1);
        __syncthreads();

        float acc[8][4];
        #pragma unroll
        for (int i = 0; i < 8; i++)
            #pragma unroll
            for (int e = 0; e < 4; e++) acc[i][e] = 0.f;
        #pragma unroll
        for (int kk8 = 0; kk8 < 8; kk8++) {
            #pragma unroll
            for (int nt = 0; nt < 8; nt++) {
                unsigned b[2];
                b[0] = Ks[(nt * 8 + g) * FSTR + kk8 * 8 + t];
                b[1] = Ks[(nt * 8 + g) * FSTR + kk8 * 8 + t + 4];
                mma_tf32(acc[nt], qa[kk8], b);
            }
        }

        const bool dz = ((kt << 6) + 63) > (br * 128 + wq);
        float sum0 = 0.f, sum1 = 0.f;
        #pragma unroll
        for (int nt = 0; nt < 8; nt++) {
            int lc = nt * 8 + 2 * t;
            int j0 = (kt << 6) + lc;
            float kna = knf[lc], knb = knf[lc + 1];
            float s00 = acc[nt][0] * 0.125f, s01 = acc[nt][1] * 0.125f;
            float s10 = acc[nt][2] * 0.125f, s11 = acc[nt][3] * 0.125f;
            float p00 = pexp(__fdividef(s00 * s00, qn0 + kna - 2.f * s00 + EPSY));
            float p01 = pexp(__fdividef(s01 * s01, qn0 + knb - 2.f * s01 + EPSY));
            float p10 = pexp(__fdividef(s10 * s10, qn1 + kna - 2.f * s10 + EPSY));
            float p11 = pexp(__fdividef(s11 * s11, qn1 + knb - 2.f * s11 + EPSY));
            if (dz) {
                if (j0     > gi0) p00 = 0.f;
                if (j0 + 1 > gi0) p01 = 0.f;
                if (j0     > gi1) p10 = 0.f;
                if (j0 + 1 > gi1) p11 = 0.f;
            }
            sum0 += p00 + p01; sum1 += p10 + p11;
            Ps[(wq + g    ) * FSTR + lc    ] = f2tf32(p00);
            Ps[(wq + g    ) * FSTR + lc + 1] = f2tf32(p01);
            Ps[(wq + g + 8) * FSTR + lc    ] = f2tf32(p10);
            Ps[(wq + g + 8) * FSTR + lc + 1] = f2tf32(p11);
        }
        sum0 += __shfl_xor_sync(0xffffffffu, sum0, 1);
        sum0 += __shfl_xor_sync(0xffffffffu, sum0, 2);
        sum1 += __shfl_xor_sync(0xffffffffu, sum1, 1);
        sum1 += __shfl_xor_sync(0xffffffffu, sum1, 2);
        l0 += sum0; l1 += sum1;

        CP_WAIT(0);
        __syncthreads();

        if (kt < KT) {
            const float* pk = Kg + (size_t)(kt + 1) * 64 * D_ + (size_t)krow * D_ + kseg;
            #pragma unroll
            for (int j = 0; j < 4; j++) cp16(&Ks[krow*FSTR + kseg + j*4], pk + j*4);
            if (tid < 16) cp16(&knf[tid*4], kng + (kt + 1) * 64 + tid*4);
            CP_COMMIT();
        }

        #pragma unroll
        for (int kk8 = 0; kk8 < 8; kk8++) {
            unsigned a[4];
            a[0] = Ps[(wq + g    ) * FSTR + kk8 * 8 + t];
            a[1] = Ps[(wq + g + 8) * FSTR + kk8 * 8 + t];
            a[2] = Ps[(wq + g    ) * FSTR + kk8 * 8 + t + 4];
            a[3] = Ps[(wq + g + 8) * FSTR + kk8 * 8 + t + 4];
            #pragma unroll
            for (int nt = 0; nt < 8; nt++) {
                unsigned b[2];
                b[0] = Vs[(kk8 * 8 + t    ) * FSTR + nt * 8 + g];
                b[1] = Vs[(kk8 * 8 + t + 4) * FSTR + nt * 8 + g];
                mma_tf32(O[nt], a, b);
            }
        }
        __syncthreads();

        if (kt < KT) {
            const float* pv = Vg + (size_t)(kt + 1) * 64 * D_ + (size_t)krow * D_ + kseg;
            #pragma unroll
            for (int j = 0; j < 4; j++) cp16(&Vs[krow*FSTR + kseg + j*4], pv + j*4);
            CP_COMMIT();
        }
    }

    // ---- epilogue ----
    float inv0 = __fdividef(1.f, l0), inv1 = __fdividef(1.f, l1);
    int bb = bh / H_, h = bh % H_;
    size_t rr0 = (size_t)bb * T_ + br * 128 + wq + g;
    size_t rr1 = rr0 + 8;
    float* ao0 = g_ao + rr0 * C_ + h * D_;
    float* ao1 = g_ao + rr1 * C_ + h * D_;
    float n0 = 0.f, n1 = 0.f;
    #pragma unroll
    for (int nt = 0; nt < 8; nt++) {
        int lc = nt * 8 + 2 * t;
        float2 w0, w1;
        w0.x = __uint_as_float(f2tf32(O[nt][0] * inv0));
        w0.y = __uint_as_float(f2tf32(O[nt][1] * inv0));
        w1.x = __uint_as_float(f2tf32(O[nt][2] * inv1));
        w1.y = __uint_as_float(f2tf32(O[nt][3] * inv1));
        n0 += w0.x*w0.x + w0.y*w0.y;
        n1 += w1.x*w1.x + w1.y*w1.y;
        *(float2*)(ao0 + lc) = w0;
        *(float2*)(ao1 + lc) = w1;
    }
    n0 += __shfl_xor_sync(0xffffffffu, n0, 1);
    n0 += __shfl_xor_sync(0xffffffffu, n0, 2);
    n1 += __shfl_xor_sync(0xffffffffu, n1, 1);
    n1 += __shfl_xor_sync(0xffffffffu, n1, 2);
    if (t == 0) {
        g_aop[rr0 * H_ + h] = n0;
        g_aop[rr1 * H_ + h] = n1;
    }
}

// ---------------- launch ----------------
extern "C" void kernel_launch(void* const* d_in, const int* in_sizes, int n_in,
                              void* d_out, int out_size) {
    const float* x  = (const float*)d_in[0];
    const float* Wa = (const float*)d_in[2];
    const float* ba = (const float*)d_in[3];
    const float* aa = (const float*)d_in[4];
    const float* Wp = (const float*)d_in[5];
    const float* bp = (const float*)d_in[6];
    const float* ap = (const float*)d_in[7];
    float* out = (float*)d_out;

    static int attr_done = 0;
    if (!attr_done) {
        cudaFuncSetAttribute(qkv_tc,     cudaFuncAttributeMaxDynamicSharedMemorySize, GEMM_SMEM);
        cudaFuncSetAttribute(proj_tc,    cudaFuncAttributeMaxDynamicSharedMemorySize, GEMM_SMEM);
        cudaFuncSetAttribute(attn_fused, cudaFuncAttributeMaxDynamicSharedMemorySize, ATTN_SMEM);
        attr_done = 1;
    }

    float* wat; cudaGetSymbolAddress((void**)&wat, g_wat);
    float* wpt; cudaGetSymbolAddress((void**)&wpt, g_wpt);
    float* wna; cudaGetSymbolAddress((void**)&wna, g_wna);
    float* wnp; cudaGetSymbolAddress((void**)&wnp, g_wnp);

    round_x_norm<<<ROWS_/8, 256>>>(x);
    roundnorm_w <<<FA_/8, 256>>>(Wa, wat, wna, FA_);
    roundnorm_w <<<C_/8,  256>>>(Wp, wpt, wnp, C_);
    qkv_tc      <<<dim3(FA_/128, ROWS_/128), 256, GEMM_SMEM>>>(ba, aa);
    attn_fused  <<<dim3(T_/128, B_*H_), 256, ATTN_SMEM>>>();
    aon_sum     <<<ROWS_/256, 256>>>();
    proj_tc     <<<dim3(C_/128, ROWS_/128), 256, GEMM_SMEM>>>(bp, ap, out);
}

// round 15
// speedup vs baseline: 1.1492x; 1.1089x over previous
#include <cuda_runtime.h>
#include <math.h>
#include <stdint.h>

// Problem constants
#define B_   4
#define T_   1024
#define C_   768
#define H_   12
#define D_   64
#define FA_  (3*C_)          // 2304
#define BHT_ (B_*H_*T_)      // 49152
#define ROWS_ (B_*T_)        // 4096
#define EPSY (1.0f/137.0f)

// ---------------- scratch (device globals: allocation-free) ----------------
__device__ float g_q [B_*H_*T_*D_];           // tf32-rounded
__device__ float g_k [B_*H_*T_*D_];
__device__ float g_v [B_*H_*T_*D_];
__device__ float g_ao[B_*T_*C_];              // attention output, tf32-rounded
__device__ float g_xt [ROWS_*C_];             // x, tf32-rounded [m][k]
__device__ float g_wat[FA_*C_];               // W_attn^T, tf32-rounded [n][k]
__device__ float g_wpt[C_*C_];                // W_proj^T, tf32-rounded [n][k]
__device__ float g_xn [ROWS_];
__device__ float g_aon[ROWS_];
__device__ float g_aop[ROWS_*H_];             // per-head partial ||ao||^2
__device__ float g_wna[FA_];
__device__ float g_wnp[C_];
__device__ float g_qn [BHT_];
__device__ float g_kn [BHT_];

// ---------------- helpers ----------------
__device__ __forceinline__ unsigned f2tf32(float x) {
    unsigned r; asm("cvt.rna.tf32.f32 %0, %1;" : "=r"(r) : "f"(x)); return r;
}
__device__ __forceinline__ void mma_tf32(float* d, const unsigned* a, const unsigned* b) {
    asm volatile("mma.sync.aligned.m16n8k8.row.col.f32.tf32.tf32.f32 "
        "{%0,%1,%2,%3}, {%4,%5,%6,%7}, {%8,%9}, {%0,%1,%2,%3};"
        : "+f"(d[0]), "+f"(d[1]), "+f"(d[2]), "+f"(d[3])
        : "r"(a[0]), "r"(a[1]), "r"(a[2]), "r"(a[3]), "r"(b[0]), "r"(b[1]));
}
// tf32 fragment via ldmatrix: an 8x4-tf32 tile == an 8x8-b16 tile.
__device__ __forceinline__ void ldsm4(unsigned* r, uint32_t addr) {
    asm volatile("ldmatrix.sync.aligned.m8n8.x4.shared.b16 {%0,%1,%2,%3}, [%4];"
        : "=r"(r[0]), "=r"(r[1]), "=r"(r[2]), "=r"(r[3]) : "r"(addr));
}
__device__ __forceinline__ void cp16(void* smem, const void* gmem) {
    unsigned s = (unsigned)__cvta_generic_to_shared(smem);
    asm volatile("cp.async.cg.shared.global [%0], [%1], 16;" :: "r"(s), "l"(gmem));
}
#define CP_COMMIT() asm volatile("cp.async.commit_group;")
#define CP_WAIT(N)  asm volatile("cp.async.wait_group %0;" :: "n"(N))

__device__ __forceinline__ uint32_t smem_u32(const void* p) {
    uint32_t a;
    asm("{ .reg .u64 t; cvta.to.shared.u64 t, %1; cvt.u32.u64 %0, t; }" : "=r"(a) : "l"(p));
    return a;
}

// exp for yat scores: val >= 0, almost always << 1/16 -> 5-term Taylor.
__device__ __forceinline__ float pexp(float x) {
    if (x < 0.0625f)
        return 1.f + x*(1.f + x*(0.5f + x*(0.16666667f + x*0.041666667f)));
    return expf(x);
}

// ---------------- rounding / norm kernels ----------------
__global__ __launch_bounds__(256) void round_x_norm(const float* __restrict__ in) {
    int warp = threadIdx.x >> 5, lane = threadIdx.x & 31;
    int r = blockIdx.x * 8 + warp;
    const float4* src = (const float4*)(in + (size_t)r * C_);
    float4* dst = (float4*)(g_xt + (size_t)r * C_);
    float s = 0.f;
    #pragma unroll
    for (int j = 0; j < 6; j++) {
        float4 v = src[lane + j * 32];
        s += v.x*v.x + v.y*v.y + v.z*v.z + v.w*v.w;
        v.x = __uint_as_float(f2tf32(v.x));
        v.y = __uint_as_float(f2tf32(v.y));
        v.z = __uint_as_float(f2tf32(v.z));
        v.w = __uint_as_float(f2tf32(v.w));
        dst[lane + j * 32] = v;
    }
    #pragma unroll
    for (int o = 16; o; o >>= 1) s += __shfl_xor_sync(0xffffffffu, s, o);
    if (lane == 0) g_xn[r] = s;
}

// W [C_][ncols] -> transposed tf32 copy [ncols][C_] + exact col norms.
__global__ __launch_bounds__(256) void roundnorm_wT(const float* __restrict__ in,
                                                    float* __restrict__ wtout,
                                                    float* __restrict__ nout, int ncols) {
    __shared__ float sh[32][9];
    int tx = threadIdx.x & 7, ty = threadIdx.x >> 3;
    int c = blockIdx.x * 8 + tx;
    float s = 0.f;
    #pragma unroll
    for (int blk = 0; blk < 6; blk++) {
        int r0 = blk * 128 + ty * 4;
        float v0 = in[(size_t)(r0+0) * ncols + c];
        float v1 = in[(size_t)(r0+1) * ncols + c];
        float v2 = in[(size_t)(r0+2) * ncols + c];
        float v3 = in[(size_t)(r0+3) * ncols + c];
        s += v0*v0 + v1*v1 + v2*v2 + v3*v3;
        float4 w;
        w.x = __uint_as_float(f2tf32(v0));
        w.y = __uint_as_float(f2tf32(v1));
        w.z = __uint_as_float(f2tf32(v2));
        w.w = __uint_as_float(f2tf32(v3));
        *(float4*)(wtout + (size_t)c * C_ + r0) = w;
    }
    sh[ty][tx] = s; __syncthreads();
    if (threadIdx.x < 8) {
        float t = 0.f;
        #pragma unroll
        for (int i = 0; i < 32; i++) t += sh[i][threadIdx.x];
        nout[blockIdx.x * 8 + threadIdx.x] = t;
    }
}

__global__ void aon_sum() {
    int r = blockIdx.x * 256 + threadIdx.x;
    if (r >= ROWS_) return;
    float s = 0.f;
    #pragma unroll
    for (int h = 0; h < H_; h++) s += g_aop[(size_t)r * H_ + h];
    g_aon[r] = s;
}

// ============ tf32 yat GEMM: 128x128 tile, ldmatrix fragments ============
// A [m][k] and B^T [n][k] both staged 128x32, stride 36 floats (144B rows ->
// chunk index 9m mod 8 distinct -> LDSM conflict-free).
#define AST 36
#define STAGEF (2*128*AST)                 // A + B floats per stage (9216)
#define GEMM_SMEM (3*STAGEF*4)             // 110,592 B -> 2 CTAs/SM

__device__ __forceinline__ void gemm_body(const float* __restrict__ Asrc,
                                          const float* __restrict__ Bt,
                                          float acc[2][8][4],
                                          int rowBase, int colBase) {
    extern __shared__ float smf[];
    const int tid  = threadIdx.x;
    const int lane = tid & 31;
    const int warp = tid >> 5;
    const int wm = (warp & 3) * 32, wn = (warp >> 2) * 64;
    const int srow = tid >> 1, sseg = (tid & 1) * 16;
    const int NIT = C_ / 32;               // 24

    // ldmatrix per-lane offsets
    const int lq = lane >> 3, lr = lane & 7;
    const int mOff  = (lq & 1) * 8 + lr, kOffA = (lq >> 1) * 4;   // A-pattern
    const int nOffB = (lq >> 1) * 8 + lr, kOffB = (lq & 1) * 4;   // B^T-pattern
    const uint32_t sm0 = smem_u32(smf);
    const uint32_t aAddr0 = sm0 + ((wm + mOff) * AST + kOffA) * 4;
    const uint32_t bAddr0 = sm0 + 128 * AST * 4 + ((wn + nOffB) * AST + kOffB) * 4;

    const float* Abase = Asrc + (size_t)(rowBase + srow) * C_ + sseg;
    const float* Bbase = Bt   + (size_t)(colBase + srow) * C_ + sseg;

    // prologue: stages 0, 1
    #pragma unroll
    for (int st = 0; st < 2; st++) {
        float* As = smf + st * STAGEF;
        float* Bs = As + 128 * AST;
        #pragma unroll
        for (int j = 0; j < 4; j++) cp16(&As[srow*AST + sseg + j*4], Abase + st*32 + j*4);
        #pragma unroll
        for (int j = 0; j < 4; j++) cp16(&Bs[srow*AST + sseg + j*4], Bbase + st*32 + j*4);
        CP_COMMIT();
    }

    int slot = 0, pslot = 2;
    for (int it = 0; it < NIT; it++) {
        if (it < NIT - 1) { CP_WAIT(1); } else { CP_WAIT(0); }
        __syncthreads();

        if (it + 2 < NIT) {
            float* As = smf + pslot * STAGEF;
            float* Bs = As + 128 * AST;
            #pragma unroll
            for (int j = 0; j < 4; j++) cp16(&As[srow*AST + sseg + j*4], Abase + (it+2)*32 + j*4);
            #pragma unroll
            for (int j = 0; j < 4; j++) cp16(&Bs[srow*AST + sseg + j*4], Bbase + (it+2)*32 + j*4);
            CP_COMMIT();
        }

        const uint32_t sb = (uint32_t)slot * (STAGEF * 4);
        #pragma unroll
        for (int kk8 = 0; kk8 < 4; kk8++) {
            unsigned a[2][4], b[4][4];
            ldsm4(a[0], aAddr0 + sb + kk8 * 32);
            ldsm4(a[1], aAddr0 + sb + 16 * AST * 4 + kk8 * 32);
            #pragma unroll
            for (int p = 0; p < 4; p++)
                ldsm4(b[p], bAddr0 + sb + p * 16 * AST * 4 + kk8 * 32);
            #pragma unroll
            for (int mt = 0; mt < 2; mt++)
                #pragma unroll
                for (int p = 0; p < 4; p++) {
                    mma_tf32(acc[mt][2*p],   a[mt], &b[p][0]);
                    mma_tf32(acc[mt][2*p+1], a[mt], &b[p][2]);
                }
        }
        slot  = (slot  == 2) ? 0 : slot + 1;
        pslot = (pslot == 2) ? 0 : pslot + 1;
    }
}

__global__ __launch_bounds__(256) void qkv_tc(const float* __restrict__ bias,
                                              const float* __restrict__ alpha) {
    const int rowBase = blockIdx.y * 128;
    const int colBase = blockIdx.x * 128;
    float acc[2][8][4];
    #pragma unroll
    for (int i = 0; i < 2; i++)
        #pragma unroll
        for (int j = 0; j < 8; j++)
            #pragma unroll
            for (int e = 0; e < 4; e++) acc[i][j][e] = 0.f;

    gemm_body(g_xt, g_wat, acc, rowBase, colBase);

    const int lane = threadIdx.x & 31, warp = threadIdx.x >> 5;
    const int g = lane >> 2, t = lane & 3;
    const int wm = (warp & 3) * 32, wn = (warp >> 2) * 64;
    const int gg = (colBase + wn) >> 6;          // warp-uniform head group
    const int h = gg % 12;
    float* dst = (gg < 12) ? g_q : ((gg < 24) ? g_k : g_v);
    float ysc = powf(sqrtf((float)FA_) / log1pf((float)FA_), alpha[0]);

    #pragma unroll
    for (int mt = 0; mt < 2; mt++) {
        #pragma unroll
        for (int e2 = 0; e2 < 2; e2++) {
            int r = rowBase + wm + mt * 16 + g + e2 * 8;
            float xn = g_xn[r];
            int bb = r >> 10, tt = r & (T_ - 1);
            float ns = 0.f;
            float* drow = dst + (((size_t)bb * H_ + h) * T_ + tt) * D_;
            #pragma unroll
            for (int nt = 0; nt < 8; nt++) {
                #pragma unroll
                for (int e1 = 0; e1 < 2; e1++) {
                    int c = colBase + wn + nt * 8 + t * 2 + e1;
                    float dot = acc[mt][nt][e2 * 2 + e1];
                    float dist = xn + g_wna[c] - 2.f * dot;
                    float y = (__fdividef(dot * dot, dist + EPSY) + bias[c]) * ysc;
                    float yr = __uint_as_float(f2tf32(y));
                    drow[c & 63] = yr;
                    ns += yr * yr;
                }
            }
            if (gg < 24) {
                ns += __shfl_xor_sync(0xffffffffu, ns, 1);
                ns += __shfl_xor_sync(0xffffffffu, ns, 2);
                if (t == 0) {
                    float* np = (gg < 12) ? g_qn : g_kn;
                    np[((size_t)bb * H_ + h) * T_ + tt] = ns;
                }
            }
        }
    }
}

__global__ __launch_bounds__(256) void proj_tc(const float* __restrict__ bias,
                                               const float* __restrict__ alpha,
                                               float* __restrict__ out) {
    const int rowBase = blockIdx.y * 128;
    const int colBase = blockIdx.x * 128;
    float acc[2][8][4];
    #pragma unroll
    for (int i = 0; i < 2; i++)
        #pragma unroll
        for (int j = 0; j < 8; j++)
            #pragma unroll
            for (int e = 0; e < 4; e++) acc[i][j][e] = 0.f;

    gemm_body(g_ao, g_wpt, acc, rowBase, colBase);

    const int lane = threadIdx.x & 31, warp = threadIdx.x >> 5;
    const int g = lane >> 2, t = lane & 3;
    const int wm = (warp & 3) * 32, wn = (warp >> 2) * 64;
    float ysc = powf(sqrtf((float)C_) / log1pf((float)C_), alpha[0]);
    #pragma unroll
    for (int mt = 0; mt < 2; mt++) {
        #pragma unroll
        for (int e2 = 0; e2 < 2; e2++) {
            int r = rowBase + wm + mt * 16 + g + e2 * 8;
            float xn = g_aon[r];
            #pragma unroll
            for (int nt = 0; nt < 8; nt++) {
                #pragma unroll
                for (int e1 = 0; e1 < 2; e1++) {
                    int c = colBase + wn + nt * 8 + t * 2 + e1;
                    float dot = acc[mt][nt][e2 * 2 + e1];
                    float dist = xn + g_wnp[c] - 2.f * dot;
                    out[(size_t)r * C_ + c] = (__fdividef(dot * dot, dist + EPSY) + bias[c]) * ysc;
                }
            }
        }
    }
}

// ============ fused yat attention: 128 q-rows/block, 8 warps, ldmatrix ============
// Ps/Ks stride 68 (17m mod 8 distinct -> LDSM-clean); Vs stride 72 (scalar loads).
#define PST 68
#define KST 68
#define VST 72
#define PS_F (128*PST)
#define KS_F (64*KST)
#define VS_F (64*VST)
#define ATTN_SMEM ((PS_F + KS_F + VS_F + 64)*4)

__global__ __launch_bounds__(256) void attn_fused() {
    const int br = (int)gridDim.x - 1 - (int)blockIdx.x;   // big tiles first
    const int bh = blockIdx.y;
    const float* Qg = g_q + ((size_t)bh * T_ + br * 128) * D_;
    const float* Kg = g_k + (size_t)bh * T_ * D_;
    const float* Vg = g_v + (size_t)bh * T_ * D_;
    const float* kng = g_kn + bh * T_;

    extern __shared__ unsigned ash[];
    unsigned* Ps = ash;
    unsigned* Ks = ash + PS_F;
    unsigned* Vs = Ks + KS_F;
    float*   knf = (float*)(Vs + VS_F);

    const int tid = threadIdx.x, lane = tid & 31, warp = tid >> 5;
    const int g = lane >> 2, t = lane & 3;
    const int wq = warp * 16;
    const int qrow = tid >> 1, qhalf = (tid & 1) * 32;
    const int krow = tid >> 2, kseg = (tid & 3) * 16;

    // ldmatrix per-lane offsets
    const int lq = lane >> 3, lr = lane & 7;
    const int mOff  = (lq & 1) * 8 + lr, kOffA = (lq >> 1) * 4;   // A-pattern (P)
    const int nOffB = (lq >> 1) * 8 + lr, kOffB = (lq & 1) * 4;   // B^T-pattern (K)
    const uint32_t shb = smem_u32(ash);
    const uint32_t pAddr = shb + ((wq + mOff) * PST + kOffA) * 4;
    const uint32_t kAddr = shb + PS_F * 4 + (nOffB * KST + kOffB) * 4;

    {
        const float* p = Qg + (size_t)qrow * D_ + qhalf;
        #pragma unroll
        for (int j = 0; j < 8; j++) cp16(&Ps[qrow*PST + qhalf + j*4], p + j*4);
        CP_COMMIT();
        const float* pk = Kg + (size_t)krow * D_ + kseg;
        #pragma unroll
        for (int j = 0; j < 4; j++) cp16(&Ks[krow*KST + kseg + j*4], pk + j*4);
        if (tid < 16) cp16(&knf[tid*4], kng + tid*4);
        CP_COMMIT();
        const float* pv = Vg + (size_t)krow * D_ + kseg;
        #pragma unroll
        for (int j = 0; j < 4; j++) cp16(&Vs[krow*VST + kseg + j*4], pv + j*4);
        CP_COMMIT();
    }
    CP_WAIT(2);
    __syncwarp();

    unsigned qa[8][4];
    #pragma unroll
    for (int kk8 = 0; kk8 < 8; kk8++) {
        int kk = kk8 * 8;
        qa[kk8][0] = Ps[(wq + g    ) * PST + kk + t];
        qa[kk8][1] = Ps[(wq + g + 8) * PST + kk + t];
        qa[kk8][2] = Ps[(wq + g    ) * PST + kk + t + 4];
        qa[kk8][3] = Ps[(wq + g + 8) * PST + kk + t + 4];
    }
    const float qn0 = g_qn[bh * T_ + br * 128 + wq + g];
    const float qn1 = g_qn[bh * T_ + br * 128 + wq + g + 8];

    float O[8][4];
    #pragma unroll
    for (int i = 0; i < 8; i++)
        #pragma unroll
        for (int e = 0; e < 4; e++) O[i][e] = 0.f;
    float l0 = 0.f, l1 = 0.f;

    const int gi0 = br * 128 + wq + g;
    const int gi1 = gi0 + 8;
    const int KT = 2 * br + 1;

    for (int kt = 0; kt <= KT; kt++) {
        CP_WAIT(1);
        __syncthreads();

        // ---- S = Q K^T (ldmatrix B fragments) ----
        float acc[8][4];
        #pragma unroll
        for (int i = 0; i < 8; i++)
            #pragma unroll
            for (int e = 0; e < 4; e++) acc[i][e] = 0.f;
        #pragma unroll
        for (int kk8 = 0; kk8 < 8; kk8++) {
            unsigned b[4][4];
            #pragma unroll
            for (int p = 0; p < 4; p++)
                ldsm4(b[p], kAddr + p * 16 * KST * 4 + kk8 * 32);
            #pragma unroll
            for (int p = 0; p < 4; p++) {
                mma_tf32(acc[2*p],   qa[kk8], &b[p][0]);
                mma_tf32(acc[2*p+1], qa[kk8], &b[p][2]);
            }
        }

        const bool dz = ((kt << 6) + 63) > (br * 128 + wq);
        float sum0 = 0.f, sum1 = 0.f;
        #pragma unroll
        for (int nt = 0; nt < 8; nt++) {
            int lc = nt * 8 + 2 * t;
            int j0 = (kt << 6) + lc;
            float kna = knf[lc], knb = knf[lc + 1];
            float s00 = acc[nt][0] * 0.125f, s01 = acc[nt][1] * 0.125f;
            float s10 = acc[nt][2] * 0.125f, s11 = acc[nt][3] * 0.125f;
            float p00 = pexp(__fdividef(s00 * s00, qn0 + kna - 2.f * s00 + EPSY));
            float p01 = pexp(__fdividef(s01 * s01, qn0 + knb - 2.f * s01 + EPSY));
            float p10 = pexp(__fdividef(s10 * s10, qn1 + kna - 2.f * s10 + EPSY));
            float p11 = pexp(__fdividef(s11 * s11, qn1 + knb - 2.f * s11 + EPSY));
            if (dz) {
                if (j0     > gi0) p00 = 0.f;
                if (j0 + 1 > gi0) p01 = 0.f;
                if (j0     > gi1) p10 = 0.f;
                if (j0 + 1 > gi1) p11 = 0.f;
            }
            sum0 += p00 + p01; sum1 += p10 + p11;
            Ps[(wq + g    ) * PST + lc    ] = f2tf32(p00);
            Ps[(wq + g    ) * PST + lc + 1] = f2tf32(p01);
            Ps[(wq + g + 8) * PST + lc    ] = f2tf32(p10);
            Ps[(wq + g + 8) * PST + lc + 1] = f2tf32(p11);
        }
        sum0 += __shfl_xor_sync(0xffffffffu, sum0, 1);
        sum0 += __shfl_xor_sync(0xffffffffu, sum0, 2);
        sum1 += __shfl_xor_sync(0xffffffffu, sum1, 1);
        sum1 += __shfl_xor_sync(0xffffffffu, sum1, 2);
        l0 += sum0; l1 += sum1;

        CP_WAIT(0);
        __syncthreads();

        if (kt < KT) {
            const float* pk = Kg + (size_t)(kt + 1) * 64 * D_ + (size_t)krow * D_ + kseg;
            #pragma unroll
            for (int j = 0; j < 4; j++) cp16(&Ks[krow*KST + kseg + j*4], pk + j*4);
            if (tid < 16) cp16(&knf[tid*4], kng + (kt + 1) * 64 + tid*4);
            CP_COMMIT();
        }

        // ---- O += P V (ldmatrix A fragments; V scalar) ----
        #pragma unroll
        for (int kk8 = 0; kk8 < 8; kk8++) {
            unsigned a[4];
            ldsm4(a, pAddr + kk8 * 32);
            #pragma unroll
            for (int nt = 0; nt < 8; nt++) {
                unsigned b[2];
                b[0] = Vs[(kk8 * 8 + t    ) * VST + nt * 8 + g];
                b[1] = Vs[(kk8 * 8 + t + 4) * VST + nt * 8 + g];
                mma_tf32(O[nt], a, b);
            }
        }
        __syncthreads();

        if (kt < KT) {
            const float* pv = Vg + (size_t)(kt + 1) * 64 * D_ + (size_t)krow * D_ + kseg;
            #pragma unroll
            for (int j = 0; j < 4; j++) cp16(&Vs[krow*VST + kseg + j*4], pv + j*4);
            CP_COMMIT();
        }
    }

    // ---- epilogue ----
    float inv0 = __fdividef(1.f, l0), inv1 = __fdividef(1.f, l1);
    int bb = bh / H_, h = bh % H_;
    size_t rr0 = (size_t)bb * T_ + br * 128 + wq + g;
    size_t rr1 = rr0 + 8;
    float* ao0 = g_ao + rr0 * C_ + h * D_;
    float* ao1 = g_ao + rr1 * C_ + h * D_;
    float n0 = 0.f, n1 = 0.f;
    #pragma unroll
    for (int nt = 0; nt < 8; nt++) {
        int lc = nt * 8 + 2 * t;
        float2 w0, w1;
        w0.x = __uint_as_float(f2tf32(O[nt][0] * inv0));
        w0.y = __uint_as_float(f2tf32(O[nt][1] * inv0));
        w1.x = __uint_as_float(f2tf32(O[nt][2] * inv1));
        w1.y = __uint_as_float(f2tf32(O[nt][3] * inv1));
        n0 += w0.x*w0.x + w0.y*w0.y;
        n1 += w1.x*w1.x + w1.y*w1.y;
        *(float2*)(ao0 + lc) = w0;
        *(float2*)(ao1 + lc) = w1;
    }
    n0 += __shfl_xor_sync(0xffffffffu, n0, 1);
    n0 += __shfl_xor_sync(0xffffffffu, n0, 2);
    n1 += __shfl_xor_sync(0xffffffffu, n1, 1);
    n1 += __shfl_xor_sync(0xffffffffu, n1, 2);
    if (t == 0) {
        g_aop[rr0 * H_ + h] = n0;
        g_aop[rr1 * H_ + h] = n1;
    }
}

// ---------------- launch ----------------
extern "C" void kernel_launch(void* const* d_in, const int* in_sizes, int n_in,
                              void* d_out, int out_size) {
    const float* x  = (const float*)d_in[0];
    const float* Wa = (const float*)d_in[2];
    const float* ba = (const float*)d_in[3];
    const float* aa = (const float*)d_in[4];
    const float* Wp = (const float*)d_in[5];
    const float* bp = (const float*)d_in[6];
    const float* ap = (const float*)d_in[7];
    float* out = (float*)d_out;

    static int attr_done = 0;
    if (!attr_done) {
        cudaFuncSetAttribute(qkv_tc,     cudaFuncAttributeMaxDynamicSharedMemorySize, GEMM_SMEM);
        cudaFuncSetAttribute(proj_tc,    cudaFuncAttributeMaxDynamicSharedMemorySize, GEMM_SMEM);
        cudaFuncSetAttribute(attn_fused, cudaFuncAttributeMaxDynamicSharedMemorySize, ATTN_SMEM);
        attr_done = 1;
    }

    float* wat; cudaGetSymbolAddress((void**)&wat, g_wat);
    float* wpt; cudaGetSymbolAddress((void**)&wpt, g_wpt);
    float* wna; cudaGetSymbolAddress((void**)&wna, g_wna);
    float* wnp; cudaGetSymbolAddress((void**)&wnp, g_wnp);

    round_x_norm<<<ROWS_/8, 256>>>(x);
    roundnorm_wT<<<FA_/8, 256>>>(Wa, wat, wna, FA_);
    roundnorm_wT<<<C_/8,  256>>>(Wp, wpt, wnp, C_);
    qkv_tc      <<<dim3(FA_/128, ROWS_/128), 256, GEMM_SMEM>>>(ba, aa);
    attn_fused  <<<dim3(T_/128, B_*H_), 256, ATTN_SMEM>>>();
    aon_sum     <<<ROWS_/256, 256>>>();
    proj_tc     <<<dim3(C_/128, ROWS_/128), 256, GEMM_SMEM>>>(bp, ap, out);
}